// round 1
// baseline (speedup 1.0000x reference)
#include <cuda_runtime.h>
#include <math.h>

#define BB   2
#define LL   2048
#define DD   1024
#define HH   16
#define KVH  4
#define DHH  64
#define GG   (HH / KVH)
#define MROWS (BB * LL)          // 4096

// ---------------- scratch (no allocations allowed) ----------------
__device__ float g_q[MROWS * HH * DHH];    // (b,l,h,d) 16 MB
__device__ float g_k[MROWS * KVH * DHH];   // (b,l,kv,d) 4 MB
__device__ float g_v[MROWS * KVH * DHH];   // 4 MB
__device__ float g_att[MROWS * HH * DHH];  // 16 MB

// ---------------- fp32 tiled GEMM: C[M,N] = A[M,K] @ B[K,N] ----------------
// BM=64 BN=64 BK=16, 256 threads, 4x4 microtile per thread.
__global__ __launch_bounds__(256)
void gemm_kernel(const float* __restrict__ A, const float* __restrict__ B,
                 float* __restrict__ C, int M, int N, int K) {
    constexpr int BM = 64, BN = 64, BK = 16, TM = 4, TN = 4;
    __shared__ float As[BK][BM + 4];
    __shared__ float Bs[BK][BN];

    const int tid = threadIdx.x;
    const int m0 = blockIdx.y * BM;
    const int n0 = blockIdx.x * BN;
    const int tr = tid / (BN / TN);   // 0..15
    const int tc = tid % (BN / TN);   // 0..15

    // load mappings (one float4 per thread per tile)
    const int a_m = tid >> 2;             // 0..63
    const int a_k = (tid & 3) << 2;       // 0,4,8,12
    const int b_k = tid >> 4;             // 0..15
    const int b_n = (tid & 15) << 2;      // 0..60

    float acc[TM][TN];
#pragma unroll
    for (int i = 0; i < TM; ++i)
#pragma unroll
        for (int j = 0; j < TN; ++j) acc[i][j] = 0.f;

    for (int k0 = 0; k0 < K; k0 += BK) {
        float4 av = *(const float4*)&A[(size_t)(m0 + a_m) * K + k0 + a_k];
        As[a_k + 0][a_m] = av.x;
        As[a_k + 1][a_m] = av.y;
        As[a_k + 2][a_m] = av.z;
        As[a_k + 3][a_m] = av.w;
        *(float4*)&Bs[b_k][b_n] =
            *(const float4*)&B[(size_t)(k0 + b_k) * N + n0 + b_n];
        __syncthreads();

#pragma unroll
        for (int kk = 0; kk < BK; ++kk) {
            float ar[TM], br[TN];
#pragma unroll
            for (int i = 0; i < TM; ++i) ar[i] = As[kk][tr * TM + i];
#pragma unroll
            for (int j = 0; j < TN; ++j) br[j] = Bs[kk][tc * TN + j];
#pragma unroll
            for (int i = 0; i < TM; ++i)
#pragma unroll
                for (int j = 0; j < TN; ++j) acc[i][j] += ar[i] * br[j];
        }
        __syncthreads();
    }

#pragma unroll
    for (int i = 0; i < TM; ++i) {
        float4 r = make_float4(acc[i][0], acc[i][1], acc[i][2], acc[i][3]);
        *(float4*)&C[(size_t)(m0 + tr * TM + i) * N + n0 + tc * TN] = r;
    }
}

// ---------------- RoPE (in place), layout (b, l, heads, DH) ----------------
__global__ void rope_kernel(float* __restrict__ t,
                            const float* __restrict__ cosb,
                            const float* __restrict__ sinb, int heads) {
    int i = blockIdx.x * blockDim.x + threadIdx.x;   // over B*L*heads*32
    int total = BB * LL * heads * (DHH / 2);
    if (i >= total) return;
    int d = i & 31;
    int h = (i >> 5) % heads;
    int l = (i >> 5) / heads % LL;
    int b = (i >> 5) / heads / LL;
    float* p = t + ((size_t)((b * LL + l) * heads + h)) * DHH;
    float c = cosb[l * (DHH / 2) + d];
    float s = sinb[l * (DHH / 2) + d];
    float t1 = p[d];
    float t2 = p[d + DHH / 2];
    p[d]           = t1 * c - t2 * s;
    p[d + DHH / 2] = t2 * c + t1 * s;
}

// ---------------- causal GQA flash attention ----------------
// grid: (L/64, B*H), block 64 threads. Thread t owns query row q0+t.
__global__ __launch_bounds__(64)
void attn_kernel(const float* __restrict__ q, const float* __restrict__ k,
                 const float* __restrict__ v, float* __restrict__ o) {
    constexpr int QT = 64, KT = 32;
    const int q0  = blockIdx.x * QT;
    const int bh  = blockIdx.y;
    const int b   = bh / HH;
    const int h   = bh % HH;
    const int kvh = h / GG;
    const int tid = threadIdx.x;
    const int qg  = q0 + tid;           // query index within sequence

    __shared__ float Ks[KT][DHH];
    __shared__ float Vs[KT][DHH];

    const float scale = 0.125f;         // 1/sqrt(64)
    float qr[DHH];
    const float* qptr = q + ((size_t)((b * LL + qg) * HH + h)) * DHH;
#pragma unroll
    for (int d = 0; d < DHH; d += 4) {
        float4 t = *(const float4*)&qptr[d];
        qr[d]     = t.x * scale;
        qr[d + 1] = t.y * scale;
        qr[d + 2] = t.z * scale;
        qr[d + 3] = t.w * scale;
    }

    float acc[DHH];
#pragma unroll
    for (int d = 0; d < DHH; ++d) acc[d] = 0.f;
    float m = -INFINITY, lsum = 0.f;

    const float* kbase = k + ((size_t)b * LL * KVH + kvh) * DHH;
    const float* vbase = v + ((size_t)b * LL * KVH + kvh) * DHH;
    const int ntiles = (q0 + QT) / KT;

    for (int t = 0; t < ntiles; ++t) {
        const int kb = t * KT;
        // cooperative tile load: 512 float4, 64 threads -> 8 iters
        for (int i = tid; i < KT * DHH / 4; i += 64) {
            int row = i >> 4;
            int col = (i & 15) << 2;
            size_t goff = (size_t)(kb + row) * KVH * DHH + col;
            *(float4*)&Ks[row][col] = *(const float4*)&kbase[goff];
            *(float4*)&Vs[row][col] = *(const float4*)&vbase[goff];
        }
        __syncthreads();

        float s[KT];
#pragma unroll
        for (int j = 0; j < KT; ++j) s[j] = 0.f;
#pragma unroll
        for (int d = 0; d < DHH; d += 4) {
            float4 qd = *(float4*)&qr[d];
#pragma unroll
            for (int j = 0; j < KT; ++j) {
                float4 kd = *(float4*)&Ks[j][d];
                s[j] += qd.x * kd.x + qd.y * kd.y + qd.z * kd.z + qd.w * kd.w;
            }
        }

        float tmax = -INFINITY;
#pragma unroll
        for (int j = 0; j < KT; ++j) {
            if (kb + j > qg) s[j] = -INFINITY;
            tmax = fmaxf(tmax, s[j]);
        }
        float mnew  = fmaxf(m, tmax);
        float alpha = __expf(m - mnew);   // 0 on first tile (m = -inf)
        float psum  = 0.f;
#pragma unroll
        for (int j = 0; j < KT; ++j) {
            s[j] = __expf(s[j] - mnew);   // reuse s[] as p[]
            psum += s[j];
        }
        lsum = lsum * alpha + psum;
        m = mnew;

#pragma unroll
        for (int d = 0; d < DHH; d += 4) {
            float4 a4 = *(float4*)&acc[d];
            a4.x *= alpha; a4.y *= alpha; a4.z *= alpha; a4.w *= alpha;
#pragma unroll
            for (int j = 0; j < KT; ++j) {
                float4 v4 = *(float4*)&Vs[j][d];
                a4.x += s[j] * v4.x;
                a4.y += s[j] * v4.y;
                a4.z += s[j] * v4.z;
                a4.w += s[j] * v4.w;
            }
            *(float4*)&acc[d] = a4;
        }
        __syncthreads();
    }

    const float inv = 1.f / lsum;
    float* optr = o + ((size_t)((b * LL + qg) * HH + h)) * DHH;
#pragma unroll
    for (int d = 0; d < DHH; d += 4) {
        float4 r = make_float4(acc[d] * inv, acc[d + 1] * inv,
                               acc[d + 2] * inv, acc[d + 3] * inv);
        *(float4*)&optr[d] = r;
    }
}

// ---------------- launch ----------------
extern "C" void kernel_launch(void* const* d_in, const int* in_sizes, int n_in,
                              void* d_out, int out_size) {
    const float* x  = (const float*)d_in[0];
    const float* rc = (const float*)d_in[1];
    const float* rs = (const float*)d_in[2];
    const float* Wq = (const float*)d_in[3];
    const float* Wk = (const float*)d_in[4];
    const float* Wv = (const float*)d_in[5];
    const float* Wo = (const float*)d_in[6];
    float* out = (float*)d_out;

    float *q, *k, *v, *att;
    cudaGetSymbolAddress((void**)&q,   g_q);
    cudaGetSymbolAddress((void**)&k,   g_k);
    cudaGetSymbolAddress((void**)&v,   g_v);
    cudaGetSymbolAddress((void**)&att, g_att);

    // QKV projections
    gemm_kernel<<<dim3(HH * DHH / 64, MROWS / 64), 256>>>(x, Wq, q, MROWS, HH * DHH, DD);
    gemm_kernel<<<dim3(KVH * DHH / 64, MROWS / 64), 256>>>(x, Wk, k, MROWS, KVH * DHH, DD);
    gemm_kernel<<<dim3(KVH * DHH / 64, MROWS / 64), 256>>>(x, Wv, v, MROWS, KVH * DHH, DD);

    // RoPE on q and k
    {
        int tq = BB * LL * HH * (DHH / 2);
        rope_kernel<<<(tq + 255) / 256, 256>>>(q, rc, rs, HH);
        int tk = BB * LL * KVH * (DHH / 2);
        rope_kernel<<<(tk + 255) / 256, 256>>>(k, rc, rs, KVH);
    }

    // attention
    attn_kernel<<<dim3(LL / 64, BB * HH), 64>>>(q, k, v, att);

    // output projection -> d_out
    gemm_kernel<<<dim3(DD / 64, MROWS / 64), 256>>>(att, Wo, out, MROWS, DD, DD);
}

// round 3
// speedup vs baseline: 1.2162x; 1.2162x over previous
#include <cuda_runtime.h>
#include <math.h>
#include <stdint.h>

#define BB   2
#define LL   2048
#define DD   1024
#define HH   16
#define KVH  4
#define DHH  64
#define GG   (HH / KVH)
#define MROWS (BB * LL)          // 4096

// ---------------- scratch (no allocations allowed) ----------------
__device__ float g_q[MROWS * HH * DHH];    // (b,l,h,d) 16 MB
__device__ float g_k[MROWS * KVH * DHH];   // (b,l,kv,d) 4 MB
__device__ float g_v[MROWS * KVH * DHH];   // 4 MB
__device__ float g_att[MROWS * HH * DHH];  // 16 MB

// ---------------- tf32 helpers ----------------
__device__ __forceinline__ uint32_t f2tf32(float f) {
    uint32_t u;
    asm("cvt.rna.tf32.f32 %0, %1;" : "=r"(u) : "f"(f));
    return u;
}

__device__ __forceinline__ void mma_tf32(float* d, const uint32_t* a, const uint32_t* b) {
    asm volatile(
        "mma.sync.aligned.m16n8k8.row.col.f32.tf32.tf32.f32 "
        "{%0,%1,%2,%3}, {%4,%5,%6,%7}, {%8,%9}, {%0,%1,%2,%3};\n"
        : "+f"(d[0]), "+f"(d[1]), "+f"(d[2]), "+f"(d[3])
        : "r"(a[0]), "r"(a[1]), "r"(a[2]), "r"(a[3]), "r"(b[0]), "r"(b[1]));
}

// ---------------- tf32 tensor-core GEMM: C[M,N] = A[M,K] @ B[K,N] ----------------
// BM=128 BN=64 BK=32, 256 threads (8 warps in 4x2), warp tile 32x32.
__global__ __launch_bounds__(256)
void gemm_tf32_kernel(const float* __restrict__ A, const float* __restrict__ B,
                      float* __restrict__ C, int M, int N, int K) {
    constexpr int BM = 128, BN = 64, BK = 32;
    constexpr int AST = BK + 4;   // 36: bank = (4m + k) % 32, conflict-free frags
    constexpr int BST = BN + 8;   // 72: bank = (8k + n) % 32, conflict-free frags
    __shared__ uint32_t As[BM * AST];
    __shared__ uint32_t Bs[BK * BST];

    const int tid  = threadIdx.x;
    const int wid  = tid >> 5;
    const int lane = tid & 31;
    const int warpM = wid & 3;      // 0..3
    const int warpN = wid >> 2;     // 0..1
    const int m0 = blockIdx.y * BM;
    const int n0 = blockIdx.x * BN;
    const int g = lane >> 2;        // 0..7
    const int t = lane & 3;         // 0..3

    float acc[2][4][4];
#pragma unroll
    for (int i = 0; i < 2; ++i)
#pragma unroll
        for (int j = 0; j < 4; ++j)
#pragma unroll
            for (int r = 0; r < 4; ++r) acc[i][j][r] = 0.f;

    for (int k0 = 0; k0 < K; k0 += BK) {
        // A tile 128x32: 1024 float4 / 256 thr = 4 each. Convert to tf32 in smem.
#pragma unroll
        for (int i = tid; i < BM * BK / 4; i += 256) {
            int m  = i >> 3;            // 8 float4 per row
            int k4 = (i & 7) << 2;
            float4 v = *(const float4*)&A[(size_t)(m0 + m) * K + k0 + k4];
            uint32_t* p = &As[m * AST + k4];
            p[0] = f2tf32(v.x); p[1] = f2tf32(v.y);
            p[2] = f2tf32(v.z); p[3] = f2tf32(v.w);
        }
        // B tile 32x64: 512 float4 / 256 thr = 2 each.
#pragma unroll
        for (int i = tid; i < BK * BN / 4; i += 256) {
            int k  = i >> 4;            // 16 float4 per row
            int n4 = (i & 15) << 2;
            float4 v = *(const float4*)&B[(size_t)(k0 + k) * N + n0 + n4];
            uint32_t* p = &Bs[k * BST + n4];
            p[0] = f2tf32(v.x); p[1] = f2tf32(v.y);
            p[2] = f2tf32(v.z); p[3] = f2tf32(v.w);
        }
        __syncthreads();

#pragma unroll
        for (int ks = 0; ks < BK / 8; ++ks) {
            uint32_t af[2][4], bf[4][2];
#pragma unroll
            for (int mt = 0; mt < 2; ++mt) {
                int mrow = warpM * 32 + mt * 16 + g;
                int kb = ks * 8 + t;
                af[mt][0] = As[mrow * AST + kb];
                af[mt][1] = As[(mrow + 8) * AST + kb];
                af[mt][2] = As[mrow * AST + kb + 4];
                af[mt][3] = As[(mrow + 8) * AST + kb + 4];
            }
#pragma unroll
            for (int nt = 0; nt < 4; ++nt) {
                int ncol = warpN * 32 + nt * 8 + g;
                int kb = ks * 8 + t;
                bf[nt][0] = Bs[kb * BST + ncol];
                bf[nt][1] = Bs[(kb + 4) * BST + ncol];
            }
#pragma unroll
            for (int mt = 0; mt < 2; ++mt)
#pragma unroll
                for (int nt = 0; nt < 4; ++nt)
                    mma_tf32(acc[mt][nt], af[mt], bf[nt]);
        }
        __syncthreads();
    }

    // epilogue: c0,c1 consecutive cols -> float2 stores
#pragma unroll
    for (int mt = 0; mt < 2; ++mt) {
#pragma unroll
        for (int nt = 0; nt < 4; ++nt) {
            int row = m0 + warpM * 32 + mt * 16 + g;
            int col = n0 + warpN * 32 + nt * 8 + t * 2;
            *(float2*)&C[(size_t)row * N + col] =
                make_float2(acc[mt][nt][0], acc[mt][nt][1]);
            *(float2*)&C[(size_t)(row + 8) * N + col] =
                make_float2(acc[mt][nt][2], acc[mt][nt][3]);
        }
    }
}

// ---------------- RoPE (in place), layout (b, l, heads, DH) ----------------
__global__ void rope_kernel(float* __restrict__ t,
                            const float* __restrict__ cosb,
                            const float* __restrict__ sinb, int heads) {
    int i = blockIdx.x * blockDim.x + threadIdx.x;
    int total = BB * LL * heads * (DHH / 2);
    if (i >= total) return;
    int d = i & 31;
    int h = (i >> 5) % heads;
    int l = (i >> 5) / heads % LL;
    int b = (i >> 5) / heads / LL;
    float* p = t + ((size_t)((b * LL + l) * heads + h)) * DHH;
    float c = cosb[l * (DHH / 2) + d];
    float s = sinb[l * (DHH / 2) + d];
    float t1 = p[d];
    float t2 = p[d + DHH / 2];
    p[d]           = t1 * c - t2 * s;
    p[d + DHH / 2] = t2 * c + t1 * s;
}

// ---------------- causal GQA flash attention ----------------
__global__ __launch_bounds__(64)
void attn_kernel(const float* __restrict__ q, const float* __restrict__ k,
                 const float* __restrict__ v, float* __restrict__ o) {
    constexpr int QT = 64, KT = 32;
    const int q0  = blockIdx.x * QT;
    const int bh  = blockIdx.y;
    const int b   = bh / HH;
    const int h   = bh % HH;
    const int kvh = h / GG;
    const int tid = threadIdx.x;
    const int qg  = q0 + tid;

    __shared__ float Ks[KT][DHH];
    __shared__ float Vs[KT][DHH];

    const float scale = 0.125f;
    float qr[DHH];
    const float* qptr = q + ((size_t)((b * LL + qg) * HH + h)) * DHH;
#pragma unroll
    for (int d = 0; d < DHH; d += 4) {
        float4 tq = *(const float4*)&qptr[d];
        qr[d]     = tq.x * scale;
        qr[d + 1] = tq.y * scale;
        qr[d + 2] = tq.z * scale;
        qr[d + 3] = tq.w * scale;
    }

    float acc[DHH];
#pragma unroll
    for (int d = 0; d < DHH; ++d) acc[d] = 0.f;
    float m = -INFINITY, lsum = 0.f;

    const float* kbase = k + ((size_t)b * LL * KVH + kvh) * DHH;
    const float* vbase = v + ((size_t)b * LL * KVH + kvh) * DHH;
    const int ntiles = (q0 + QT) / KT;

    for (int ti = 0; ti < ntiles; ++ti) {
        const int kb = ti * KT;
        for (int i = tid; i < KT * DHH / 4; i += 64) {
            int row = i >> 4;
            int col = (i & 15) << 2;
            size_t goff = (size_t)(kb + row) * KVH * DHH + col;
            *(float4*)&Ks[row][col] = *(const float4*)&kbase[goff];
            *(float4*)&Vs[row][col] = *(const float4*)&vbase[goff];
        }
        __syncthreads();

        float s[KT];
#pragma unroll
        for (int j = 0; j < KT; ++j) s[j] = 0.f;
#pragma unroll
        for (int d = 0; d < DHH; d += 4) {
            float4 qd = *(float4*)&qr[d];
#pragma unroll
            for (int j = 0; j < KT; ++j) {
                float4 kd = *(float4*)&Ks[j][d];
                s[j] += qd.x * kd.x + qd.y * kd.y + qd.z * kd.z + qd.w * kd.w;
            }
        }

        float tmax = -INFINITY;
#pragma unroll
        for (int j = 0; j < KT; ++j) {
            if (kb + j > qg) s[j] = -INFINITY;
            tmax = fmaxf(tmax, s[j]);
        }
        float mnew  = fmaxf(m, tmax);
        float alpha = __expf(m - mnew);
        float psum  = 0.f;
#pragma unroll
        for (int j = 0; j < KT; ++j) {
            s[j] = __expf(s[j] - mnew);
            psum += s[j];
        }
        lsum = lsum * alpha + psum;
        m = mnew;

#pragma unroll
        for (int d = 0; d < DHH; d += 4) {
            float4 a4 = *(float4*)&acc[d];
            a4.x *= alpha; a4.y *= alpha; a4.z *= alpha; a4.w *= alpha;
#pragma unroll
            for (int j = 0; j < KT; ++j) {
                float4 v4 = *(float4*)&Vs[j][d];
                a4.x += s[j] * v4.x;
                a4.y += s[j] * v4.y;
                a4.z += s[j] * v4.z;
                a4.w += s[j] * v4.w;
            }
            *(float4*)&acc[d] = a4;
        }
        __syncthreads();
    }

    const float inv = 1.f / lsum;
    float* optr = o + ((size_t)((b * LL + qg) * HH + h)) * DHH;
#pragma unroll
    for (int d = 0; d < DHH; d += 4) {
        float4 r = make_float4(acc[d] * inv, acc[d + 1] * inv,
                               acc[d + 2] * inv, acc[d + 3] * inv);
        *(float4*)&optr[d] = r;
    }
}

// ---------------- launch ----------------
extern "C" void kernel_launch(void* const* d_in, const int* in_sizes, int n_in,
                              void* d_out, int out_size) {
    const float* x  = (const float*)d_in[0];
    const float* rc = (const float*)d_in[1];
    const float* rs = (const float*)d_in[2];
    const float* Wq = (const float*)d_in[3];
    const float* Wk = (const float*)d_in[4];
    const float* Wv = (const float*)d_in[5];
    const float* Wo = (const float*)d_in[6];
    float* out = (float*)d_out;

    float *q, *k, *v, *att;
    cudaGetSymbolAddress((void**)&q,   g_q);
    cudaGetSymbolAddress((void**)&k,   g_k);
    cudaGetSymbolAddress((void**)&v,   g_v);
    cudaGetSymbolAddress((void**)&att, g_att);

    // QKV projections (tf32 tensor cores)
    gemm_tf32_kernel<<<dim3(HH * DHH / 64, MROWS / 128), 256>>>(x, Wq, q, MROWS, HH * DHH, DD);
    gemm_tf32_kernel<<<dim3(KVH * DHH / 64, MROWS / 128), 256>>>(x, Wk, k, MROWS, KVH * DHH, DD);
    gemm_tf32_kernel<<<dim3(KVH * DHH / 64, MROWS / 128), 256>>>(x, Wv, v, MROWS, KVH * DHH, DD);

    // RoPE on q and k
    {
        int tq = BB * LL * HH * (DHH / 2);
        rope_kernel<<<(tq + 255) / 256, 256>>>(q, rc, rs, HH);
        int tk = BB * LL * KVH * (DHH / 2);
        rope_kernel<<<(tk + 255) / 256, 256>>>(k, rc, rs, KVH);
    }

    // attention
    attn_kernel<<<dim3(LL / 64, BB * HH), 64>>>(q, k, v, att);

    // output projection -> d_out (tf32 tensor cores)
    gemm_tf32_kernel<<<dim3(DD / 64, MROWS / 128), 256>>>(att, Wo, out, MROWS, DD, DD);
}

// round 4
// speedup vs baseline: 3.8239x; 3.1441x over previous
#include <cuda_runtime.h>
#include <math.h>
#include <stdint.h>

#define BB   2
#define LL   2048
#define DD   1024
#define HH   16
#define KVH  4
#define DHH  64
#define GG   (HH / KVH)
#define MROWS (BB * LL)          // 4096

// ---------------- scratch (no allocations allowed) ----------------
__device__ float g_q[MROWS * HH * DHH];    // (b,l,h,d) 16 MB
__device__ float g_k[MROWS * KVH * DHH];   // (b,l,kv,d) 4 MB
__device__ float g_v[MROWS * KVH * DHH];   // 4 MB
__device__ float g_att[MROWS * HH * DHH];  // 16 MB

// ---------------- tf32 helpers ----------------
__device__ __forceinline__ uint32_t f2tf32(float f) {
    uint32_t u;
    asm("cvt.rna.tf32.f32 %0, %1;" : "=r"(u) : "f"(f));
    return u;
}

__device__ __forceinline__ void mma_tf32(float* d, const uint32_t* a, const uint32_t* b) {
    asm volatile(
        "mma.sync.aligned.m16n8k8.row.col.f32.tf32.tf32.f32 "
        "{%0,%1,%2,%3}, {%4,%5,%6,%7}, {%8,%9}, {%0,%1,%2,%3};\n"
        : "+f"(d[0]), "+f"(d[1]), "+f"(d[2]), "+f"(d[3])
        : "r"(a[0]), "r"(a[1]), "r"(a[2]), "r"(a[3]), "r"(b[0]), "r"(b[1]));
}

// ---------------- tf32 tensor-core GEMM: C[M,N] = A[M,K] @ B[K,N] ----------------
__global__ __launch_bounds__(256)
void gemm_tf32_kernel(const float* __restrict__ A, const float* __restrict__ B,
                      float* __restrict__ C, int M, int N, int K) {
    constexpr int BM = 128, BN = 64, BK = 32;
    constexpr int AST = BK + 4;   // 36
    constexpr int BST = BN + 8;   // 72
    __shared__ uint32_t As[BM * AST];
    __shared__ uint32_t Bs[BK * BST];

    const int tid  = threadIdx.x;
    const int wid  = tid >> 5;
    const int lane = tid & 31;
    const int warpM = wid & 3;
    const int warpN = wid >> 2;
    const int m0 = blockIdx.y * BM;
    const int n0 = blockIdx.x * BN;
    const int g = lane >> 2;
    const int t = lane & 3;

    float acc[2][4][4];
#pragma unroll
    for (int i = 0; i < 2; ++i)
#pragma unroll
        for (int j = 0; j < 4; ++j)
#pragma unroll
            for (int r = 0; r < 4; ++r) acc[i][j][r] = 0.f;

    for (int k0 = 0; k0 < K; k0 += BK) {
#pragma unroll
        for (int i = tid; i < BM * BK / 4; i += 256) {
            int m  = i >> 3;
            int k4 = (i & 7) << 2;
            float4 v = *(const float4*)&A[(size_t)(m0 + m) * K + k0 + k4];
            uint32_t* p = &As[m * AST + k4];
            p[0] = f2tf32(v.x); p[1] = f2tf32(v.y);
            p[2] = f2tf32(v.z); p[3] = f2tf32(v.w);
        }
#pragma unroll
        for (int i = tid; i < BK * BN / 4; i += 256) {
            int k  = i >> 4;
            int n4 = (i & 15) << 2;
            float4 v = *(const float4*)&B[(size_t)(k0 + k) * N + n0 + n4];
            uint32_t* p = &Bs[k * BST + n4];
            p[0] = f2tf32(v.x); p[1] = f2tf32(v.y);
            p[2] = f2tf32(v.z); p[3] = f2tf32(v.w);
        }
        __syncthreads();

#pragma unroll
        for (int ks = 0; ks < BK / 8; ++ks) {
            uint32_t af[2][4], bf[4][2];
#pragma unroll
            for (int mt = 0; mt < 2; ++mt) {
                int mrow = warpM * 32 + mt * 16 + g;
                int kb = ks * 8 + t;
                af[mt][0] = As[mrow * AST + kb];
                af[mt][1] = As[(mrow + 8) * AST + kb];
                af[mt][2] = As[mrow * AST + kb + 4];
                af[mt][3] = As[(mrow + 8) * AST + kb + 4];
            }
#pragma unroll
            for (int nt = 0; nt < 4; ++nt) {
                int ncol = warpN * 32 + nt * 8 + g;
                int kb = ks * 8 + t;
                bf[nt][0] = Bs[kb * BST + ncol];
                bf[nt][1] = Bs[(kb + 4) * BST + ncol];
            }
#pragma unroll
            for (int mt = 0; mt < 2; ++mt)
#pragma unroll
                for (int nt = 0; nt < 4; ++nt)
                    mma_tf32(acc[mt][nt], af[mt], bf[nt]);
        }
        __syncthreads();
    }

#pragma unroll
    for (int mt = 0; mt < 2; ++mt) {
#pragma unroll
        for (int nt = 0; nt < 4; ++nt) {
            int row = m0 + warpM * 32 + mt * 16 + g;
            int col = n0 + warpN * 32 + nt * 8 + t * 2;
            *(float2*)&C[(size_t)row * N + col] =
                make_float2(acc[mt][nt][0], acc[mt][nt][1]);
            *(float2*)&C[(size_t)(row + 8) * N + col] =
                make_float2(acc[mt][nt][2], acc[mt][nt][3]);
        }
    }
}

// ---------------- RoPE (in place), layout (b, l, heads, DH) ----------------
__global__ void rope_kernel(float* __restrict__ t,
                            const float* __restrict__ cosb,
                            const float* __restrict__ sinb, int heads) {
    int i = blockIdx.x * blockDim.x + threadIdx.x;
    int total = BB * LL * heads * (DHH / 2);
    if (i >= total) return;
    int d = i & 31;
    int h = (i >> 5) % heads;
    int l = (i >> 5) / heads % LL;
    int b = (i >> 5) / heads / LL;
    float* p = t + ((size_t)((b * LL + l) * heads + h)) * DHH;
    float c = cosb[l * (DHH / 2) + d];
    float s = sinb[l * (DHH / 2) + d];
    float t1 = p[d];
    float t2 = p[d + DHH / 2];
    p[d]           = t1 * c - t2 * s;
    p[d + DHH / 2] = t2 * c + t1 * s;
}

// ---------------- tf32 tensor-core causal GQA flash attention ----------------
// block = 128 threads (4 warps). QT=64 (16 rows/warp), KT=64, DH=64.
// SMEM: Ks[64][68] tf32, Vs[64][72] tf32, Ps[4][16][68] tf32 (warp-private P).
#define KST 68
#define VST 72
__global__ __launch_bounds__(128)
void attn_mma_kernel(const float* __restrict__ q, const float* __restrict__ k,
                     const float* __restrict__ v, float* __restrict__ o) {
    extern __shared__ uint32_t sm[];
    uint32_t* Ks = sm;                       // 64*68 = 4352 words
    uint32_t* Vs = sm + 64 * KST;            // 64*72 = 4608
    uint32_t* Ps = sm + 64 * KST + 64 * VST; // 4*16*68 = 4352

    const int bx  = gridDim.x - 1 - blockIdx.x;   // longest blocks first
    const int bh  = blockIdx.y;
    const int b   = bh / HH;
    const int h   = bh % HH;
    const int kvh = h / GG;
    const int q0  = bx * 64;
    const int tid = threadIdx.x;
    const int wid = tid >> 5;
    const int lane = tid & 31;
    const int g = lane >> 2;
    const int t = lane & 3;

    // ---- stage Q tile (scaled, tf32) into Ps, then extract per-warp fragments
    const float* qbase = q + ((size_t)((b * LL + q0) * HH + h)) * DHH;
#pragma unroll
    for (int i = tid; i < 64 * 64 / 4; i += 128) {
        int row = i >> 4;
        int c4  = (i & 15) << 2;
        float4 tv = *(const float4*)&qbase[(size_t)row * HH * DHH + c4];
        uint32_t* p = &Ps[row * KST + c4];
        p[0] = f2tf32(tv.x * 0.125f);
        p[1] = f2tf32(tv.y * 0.125f);
        p[2] = f2tf32(tv.z * 0.125f);
        p[3] = f2tf32(tv.w * 0.125f);
    }
    __syncthreads();

    uint32_t qf[8][4];
    {
        int r0 = wid * 16 + g;
#pragma unroll
        for (int ks = 0; ks < 8; ++ks) {
            qf[ks][0] = Ps[r0 * KST + ks * 8 + t];
            qf[ks][1] = Ps[(r0 + 8) * KST + ks * 8 + t];
            qf[ks][2] = Ps[r0 * KST + ks * 8 + t + 4];
            qf[ks][3] = Ps[(r0 + 8) * KST + ks * 8 + t + 4];
        }
    }
    // each warp henceforth touches only its own Ps region -> no barrier needed

    float o_acc[8][4];
#pragma unroll
    for (int nt = 0; nt < 8; ++nt)
#pragma unroll
        for (int r = 0; r < 4; ++r) o_acc[nt][r] = 0.f;
    float m0 = -INFINITY, m1 = -INFINITY, l0 = 0.f, l1 = 0.f;

    const float* kbase = k + ((size_t)b * LL * KVH + kvh) * DHH;
    const float* vbase = v + ((size_t)b * LL * KVH + kvh) * DHH;
    uint32_t* Pw = Ps + wid * 16 * KST;
    const int ntiles = bx + 1;

    for (int ti = 0; ti < ntiles; ++ti) {
        const int kb = ti * 64;
        // ---- load K,V tiles (tf32)
#pragma unroll
        for (int i = tid; i < 64 * 64 / 4; i += 128) {
            int row = i >> 4;
            int c4  = (i & 15) << 2;
            size_t goff = (size_t)(kb + row) * KVH * DHH + c4;
            float4 kv4 = *(const float4*)&kbase[goff];
            uint32_t* pk = &Ks[row * KST + c4];
            pk[0] = f2tf32(kv4.x); pk[1] = f2tf32(kv4.y);
            pk[2] = f2tf32(kv4.z); pk[3] = f2tf32(kv4.w);
            float4 vv4 = *(const float4*)&vbase[goff];
            uint32_t* pv = &Vs[row * VST + c4];
            pv[0] = f2tf32(vv4.x); pv[1] = f2tf32(vv4.y);
            pv[2] = f2tf32(vv4.z); pv[3] = f2tf32(vv4.w);
        }
        __syncthreads();

        // ---- S = Q @ K^T (B operand = natural Ks[key][d])
        float s_acc[8][4];
#pragma unroll
        for (int nt = 0; nt < 8; ++nt)
#pragma unroll
            for (int r = 0; r < 4; ++r) s_acc[nt][r] = 0.f;
#pragma unroll
        for (int ks = 0; ks < 8; ++ks) {
            uint32_t bfr[8][2];
#pragma unroll
            for (int nt = 0; nt < 8; ++nt) {
                bfr[nt][0] = Ks[(nt * 8 + g) * KST + ks * 8 + t];
                bfr[nt][1] = Ks[(nt * 8 + g) * KST + ks * 8 + t + 4];
            }
#pragma unroll
            for (int nt = 0; nt < 8; ++nt) mma_tf32(s_acc[nt], qf[ks], bfr[nt]);
        }

        // ---- causal mask (diagonal tile only: kb == q0)
        const int wr = wid * 16 + g;            // local row of c0/c1
        if (ti == ntiles - 1) {
#pragma unroll
            for (int nt = 0; nt < 8; ++nt) {
                int c = nt * 8 + 2 * t;
                if (c > wr)          s_acc[nt][0] = -INFINITY;
                if (c + 1 > wr)      s_acc[nt][1] = -INFINITY;
                if (c > wr + 8)      s_acc[nt][2] = -INFINITY;
                if (c + 1 > wr + 8)  s_acc[nt][3] = -INFINITY;
            }
        }

        // ---- online softmax (rows wr and wr+8)
        float tm0 = -INFINITY, tm1 = -INFINITY;
#pragma unroll
        for (int nt = 0; nt < 8; ++nt) {
            tm0 = fmaxf(tm0, fmaxf(s_acc[nt][0], s_acc[nt][1]));
            tm1 = fmaxf(tm1, fmaxf(s_acc[nt][2], s_acc[nt][3]));
        }
        tm0 = fmaxf(tm0, __shfl_xor_sync(0xffffffff, tm0, 1));
        tm0 = fmaxf(tm0, __shfl_xor_sync(0xffffffff, tm0, 2));
        tm1 = fmaxf(tm1, __shfl_xor_sync(0xffffffff, tm1, 1));
        tm1 = fmaxf(tm1, __shfl_xor_sync(0xffffffff, tm1, 2));
        float mn0 = fmaxf(m0, tm0), mn1 = fmaxf(m1, tm1);
        float a0 = __expf(m0 - mn0), a1 = __expf(m1 - mn1);
        float ps0 = 0.f, ps1 = 0.f;
#pragma unroll
        for (int nt = 0; nt < 8; ++nt) {
            s_acc[nt][0] = __expf(s_acc[nt][0] - mn0);
            s_acc[nt][1] = __expf(s_acc[nt][1] - mn0);
            s_acc[nt][2] = __expf(s_acc[nt][2] - mn1);
            s_acc[nt][3] = __expf(s_acc[nt][3] - mn1);
            ps0 += s_acc[nt][0] + s_acc[nt][1];
            ps1 += s_acc[nt][2] + s_acc[nt][3];
        }
        ps0 += __shfl_xor_sync(0xffffffff, ps0, 1);
        ps0 += __shfl_xor_sync(0xffffffff, ps0, 2);
        ps1 += __shfl_xor_sync(0xffffffff, ps1, 1);
        ps1 += __shfl_xor_sync(0xffffffff, ps1, 2);
        l0 = l0 * a0 + ps0;
        l1 = l1 * a1 + ps1;
        m0 = mn0; m1 = mn1;

        // ---- write P (warp-private) as tf32
#pragma unroll
        for (int nt = 0; nt < 8; ++nt) {
            int c = nt * 8 + 2 * t;
            Pw[g * KST + c]           = f2tf32(s_acc[nt][0]);
            Pw[g * KST + c + 1]       = f2tf32(s_acc[nt][1]);
            Pw[(g + 8) * KST + c]     = f2tf32(s_acc[nt][2]);
            Pw[(g + 8) * KST + c + 1] = f2tf32(s_acc[nt][3]);
        }
        __syncwarp();

        // ---- rescale O, then O += P @ V
#pragma unroll
        for (int nt = 0; nt < 8; ++nt) {
            o_acc[nt][0] *= a0; o_acc[nt][1] *= a0;
            o_acc[nt][2] *= a1; o_acc[nt][3] *= a1;
        }
#pragma unroll
        for (int ks = 0; ks < 8; ++ks) {
            uint32_t pf[4];
            pf[0] = Pw[g * KST + ks * 8 + t];
            pf[1] = Pw[(g + 8) * KST + ks * 8 + t];
            pf[2] = Pw[g * KST + ks * 8 + t + 4];
            pf[3] = Pw[(g + 8) * KST + ks * 8 + t + 4];
            uint32_t bv[8][2];
#pragma unroll
            for (int nt = 0; nt < 8; ++nt) {
                bv[nt][0] = Vs[(ks * 8 + t) * VST + nt * 8 + g];
                bv[nt][1] = Vs[(ks * 8 + t + 4) * VST + nt * 8 + g];
            }
#pragma unroll
            for (int nt = 0; nt < 8; ++nt) mma_tf32(o_acc[nt], pf, bv[nt]);
        }
        __syncthreads();   // before next tile overwrites Ks/Vs
    }

    // ---- epilogue
    const float inv0 = 1.f / l0, inv1 = 1.f / l1;
    const int row0 = q0 + wid * 16 + g;
    float* obase = o + ((size_t)((b * LL + row0) * HH + h)) * DHH;
    float* obase8 = o + ((size_t)((b * LL + row0 + 8) * HH + h)) * DHH;
#pragma unroll
    for (int nt = 0; nt < 8; ++nt) {
        int c = nt * 8 + 2 * t;
        *(float2*)&obase[c]  = make_float2(o_acc[nt][0] * inv0, o_acc[nt][1] * inv0);
        *(float2*)&obase8[c] = make_float2(o_acc[nt][2] * inv1, o_acc[nt][3] * inv1);
    }
}

// ---------------- launch ----------------
extern "C" void kernel_launch(void* const* d_in, const int* in_sizes, int n_in,
                              void* d_out, int out_size) {
    const float* x  = (const float*)d_in[0];
    const float* rc = (const float*)d_in[1];
    const float* rs = (const float*)d_in[2];
    const float* Wq = (const float*)d_in[3];
    const float* Wk = (const float*)d_in[4];
    const float* Wv = (const float*)d_in[5];
    const float* Wo = (const float*)d_in[6];
    float* out = (float*)d_out;

    float *q, *k, *v, *att;
    cudaGetSymbolAddress((void**)&q,   g_q);
    cudaGetSymbolAddress((void**)&k,   g_k);
    cudaGetSymbolAddress((void**)&v,   g_v);
    cudaGetSymbolAddress((void**)&att, g_att);

    // QKV projections (tf32 tensor cores)
    gemm_tf32_kernel<<<dim3(HH * DHH / 64, MROWS / 128), 256>>>(x, Wq, q, MROWS, HH * DHH, DD);
    gemm_tf32_kernel<<<dim3(KVH * DHH / 64, MROWS / 128), 256>>>(x, Wk, k, MROWS, KVH * DHH, DD);
    gemm_tf32_kernel<<<dim3(KVH * DHH / 64, MROWS / 128), 256>>>(x, Wv, v, MROWS, KVH * DHH, DD);

    // RoPE on q and k
    {
        int tq = BB * LL * HH * (DHH / 2);
        rope_kernel<<<(tq + 255) / 256, 256>>>(q, rc, rs, HH);
        int tk = BB * LL * KVH * (DHH / 2);
        rope_kernel<<<(tk + 255) / 256, 256>>>(k, rc, rs, KVH);
    }

    // attention (tf32 tensor cores, flash)
    {
        const int smem = (64 * KST + 64 * VST + 4 * 16 * KST) * 4;  // 53248 B
        static bool attr_set = false;
        if (!attr_set) {
            cudaFuncSetAttribute(attn_mma_kernel,
                                 cudaFuncAttributeMaxDynamicSharedMemorySize, smem);
            attr_set = true;
        }
        attn_mma_kernel<<<dim3(LL / 64, BB * HH), 128, smem>>>(q, k, v, att);
    }

    // output projection -> d_out (tf32 tensor cores)
    gemm_tf32_kernel<<<dim3(DD / 64, MROWS / 128), 256>>>(att, Wo, out, MROWS, DD, DD);
}

// round 5
// speedup vs baseline: 4.4812x; 1.1719x over previous
#include <cuda_runtime.h>
#include <math.h>
#include <stdint.h>

#define BB   2
#define LL   2048
#define DD   1024
#define HH   16
#define KVH  4
#define DHH  64
#define GG   (HH / KVH)
#define MROWS (BB * LL)          // 4096

// ---------------- scratch (no allocations allowed) ----------------
__device__ float g_q[MROWS * HH * DHH];    // (b,l,h,d) 16 MB
__device__ float g_k[MROWS * KVH * DHH];   // 4 MB
__device__ float g_v[MROWS * KVH * DHH];   // 4 MB
__device__ float g_att[MROWS * HH * DHH];  // 16 MB

// ---------------- helpers ----------------
__device__ __forceinline__ uint32_t f2tf32(float f) {
    uint32_t u;
    asm("cvt.rna.tf32.f32 %0, %1;" : "=r"(u) : "f"(f));
    return u;
}

__device__ __forceinline__ void mma_tf32(float* d, const uint32_t* a, const uint32_t* b) {
    asm volatile(
        "mma.sync.aligned.m16n8k8.row.col.f32.tf32.tf32.f32 "
        "{%0,%1,%2,%3}, {%4,%5,%6,%7}, {%8,%9}, {%0,%1,%2,%3};\n"
        : "+f"(d[0]), "+f"(d[1]), "+f"(d[2]), "+f"(d[3])
        : "r"(a[0]), "r"(a[1]), "r"(a[2]), "r"(a[3]), "r"(b[0]), "r"(b[1]));
}

__device__ __forceinline__ uint32_t smaddr(const void* p) {
    return (uint32_t)__cvta_generic_to_shared(p);
}
__device__ __forceinline__ void cp_async16(uint32_t dst, const void* src) {
    asm volatile("cp.async.cg.shared.global [%0], [%1], 16;\n" :: "r"(dst), "l"(src));
}

// ---------------- 2-stage cp.async tf32 GEMM core ----------------
// BM=128 BN=64 BK=32, 256 threads (warps 4x2), warp tile 32x32.
// SMEM holds raw fp32; cvt to tf32 at fragment-read time.
__device__ __forceinline__ void gemm_pipe_core(const float* __restrict__ A,
                                               const float* __restrict__ B,
                                               float* __restrict__ C,
                                               int K, int NB, int n0, int m0) {
    constexpr int BM = 128, BN = 64, BK = 32;
    constexpr int AST = BK + 4;   // 36: frag bank = 4g+t (bijective)
    constexpr int BST = BN + 8;   // 72: frag bank = 8t+g (bijective)
    extern __shared__ float smf[];
    float* Asb = smf;                   // 2 * 128*36 = 9216 floats
    float* Bsb = smf + 2 * BM * AST;    // 2 * 32*72  = 4608 floats

    const int tid  = threadIdx.x;
    const int wid  = tid >> 5;
    const int lane = tid & 31;
    const int warpM = wid & 3;
    const int warpN = wid >> 2;
    const int g = lane >> 2;
    const int t = lane & 3;

    float acc[2][4][4];
#pragma unroll
    for (int i = 0; i < 2; ++i)
#pragma unroll
        for (int j = 0; j < 4; ++j)
#pragma unroll
            for (int r = 0; r < 4; ++r) acc[i][j][r] = 0.f;

    auto issue = [&](int k0, int buf) {
        float* As = Asb + buf * BM * AST;
        float* Bs = Bsb + buf * BK * BST;
#pragma unroll
        for (int i = tid; i < BM * BK / 4; i += 256) {
            int m  = i >> 3;
            int k4 = (i & 7) << 2;
            cp_async16(smaddr(&As[m * AST + k4]),
                       &A[(size_t)(m0 + m) * K + k0 + k4]);
        }
#pragma unroll
        for (int i = tid; i < BK * BN / 4; i += 256) {
            int kk = i >> 4;
            int n4 = (i & 15) << 2;
            cp_async16(smaddr(&Bs[kk * BST + n4]),
                       &B[(size_t)(k0 + kk) * NB + n0 + n4]);
        }
        asm volatile("cp.async.commit_group;\n");
    };

    issue(0, 0);
    int buf = 0;
    for (int k0 = 0; k0 < K; k0 += BK) {
        if (k0 + BK < K) {
            issue(k0 + BK, buf ^ 1);
            asm volatile("cp.async.wait_group 1;\n");
        } else {
            asm volatile("cp.async.wait_group 0;\n");
        }
        __syncthreads();

        const float* As = Asb + buf * BM * AST;
        const float* Bs = Bsb + buf * BK * BST;
#pragma unroll
        for (int ks = 0; ks < BK / 8; ++ks) {
            uint32_t af[2][4], bf[4][2];
#pragma unroll
            for (int mt = 0; mt < 2; ++mt) {
                int mrow = warpM * 32 + mt * 16 + g;
                int kb = ks * 8 + t;
                af[mt][0] = f2tf32(As[mrow * AST + kb]);
                af[mt][1] = f2tf32(As[(mrow + 8) * AST + kb]);
                af[mt][2] = f2tf32(As[mrow * AST + kb + 4]);
                af[mt][3] = f2tf32(As[(mrow + 8) * AST + kb + 4]);
            }
#pragma unroll
            for (int nt = 0; nt < 4; ++nt) {
                int ncol = warpN * 32 + nt * 8 + g;
                int kb = ks * 8 + t;
                bf[nt][0] = f2tf32(Bs[kb * BST + ncol]);
                bf[nt][1] = f2tf32(Bs[(kb + 4) * BST + ncol]);
            }
#pragma unroll
            for (int mt = 0; mt < 2; ++mt)
#pragma unroll
                for (int nt = 0; nt < 4; ++nt)
                    mma_tf32(acc[mt][nt], af[mt], bf[nt]);
        }
        __syncthreads();
        buf ^= 1;
    }

#pragma unroll
    for (int mt = 0; mt < 2; ++mt) {
#pragma unroll
        for (int nt = 0; nt < 4; ++nt) {
            int row = m0 + warpM * 32 + mt * 16 + g;
            int col = n0 + warpN * 32 + nt * 8 + t * 2;
            *(float2*)&C[(size_t)row * NB + col] =
                make_float2(acc[mt][nt][0], acc[mt][nt][1]);
            *(float2*)&C[(size_t)(row + 8) * NB + col] =
                make_float2(acc[mt][nt][2], acc[mt][nt][3]);
        }
    }
}

#define GEMM_SMEM ((2 * 128 * 36 + 2 * 32 * 72) * 4)   // 55296 B

// merged QKV projection: 24 n-tiles (16 q, 4 k, 4 v), each 64 wide
__global__ __launch_bounds__(256)
void gemm_qkv_kernel(const float* __restrict__ x,
                     const float* __restrict__ Wq, const float* __restrict__ Wk,
                     const float* __restrict__ Wv,
                     float* __restrict__ q, float* __restrict__ k,
                     float* __restrict__ v) {
    const int nt = blockIdx.x;
    const float* B;
    float* C;
    int NB, n0;
    if (nt < 16)      { B = Wq; C = q; NB = 1024; n0 = nt * 64; }
    else if (nt < 20) { B = Wk; C = k; NB = 256;  n0 = (nt - 16) * 64; }
    else              { B = Wv; C = v; NB = 256;  n0 = (nt - 20) * 64; }
    gemm_pipe_core(x, B, C, DD, NB, n0, blockIdx.y * 128);
}

// generic GEMM (output projection)
__global__ __launch_bounds__(256)
void gemm_wo_kernel(const float* __restrict__ A, const float* __restrict__ B,
                    float* __restrict__ C, int K, int NB) {
    gemm_pipe_core(A, B, C, K, NB, blockIdx.x * 64, blockIdx.y * 128);
}

// ---------------- RoPE (in place), layout (b, l, heads, DH) ----------------
__global__ void rope_kernel(float* __restrict__ t,
                            const float* __restrict__ cosb,
                            const float* __restrict__ sinb, int heads) {
    int i = blockIdx.x * blockDim.x + threadIdx.x;
    int total = BB * LL * heads * (DHH / 2);
    if (i >= total) return;
    int d = i & 31;
    int h = (i >> 5) % heads;
    int l = (i >> 5) / heads % LL;
    int b = (i >> 5) / heads / LL;
    float* p = t + ((size_t)((b * LL + l) * heads + h)) * DHH;
    float c = cosb[l * (DHH / 2) + d];
    float s = sinb[l * (DHH / 2) + d];
    float t1 = p[d];
    float t2 = p[d + DHH / 2];
    p[d]           = t1 * c - t2 * s;
    p[d + DHH / 2] = t2 * c + t1 * s;
}

// ---------------- tf32 tensor-core causal GQA flash attention ----------------
#define KST 68
#define VST 72
__global__ __launch_bounds__(128)
void attn_mma_kernel(const float* __restrict__ q, const float* __restrict__ k,
                     const float* __restrict__ v, float* __restrict__ o) {
    extern __shared__ uint32_t sm[];
    uint32_t* Ks = sm;
    uint32_t* Vs = sm + 64 * KST;
    uint32_t* Ps = sm + 64 * KST + 64 * VST;

    const int bx  = gridDim.x - 1 - blockIdx.x;
    const int bh  = blockIdx.y;
    const int b   = bh / HH;
    const int h   = bh % HH;
    const int kvh = h / GG;
    const int q0  = bx * 64;
    const int tid = threadIdx.x;
    const int wid = tid >> 5;
    const int lane = tid & 31;
    const int g = lane >> 2;
    const int t = lane & 3;

    const float* qbase = q + ((size_t)((b * LL + q0) * HH + h)) * DHH;
#pragma unroll
    for (int i = tid; i < 64 * 64 / 4; i += 128) {
        int row = i >> 4;
        int c4  = (i & 15) << 2;
        float4 tv = *(const float4*)&qbase[(size_t)row * HH * DHH + c4];
        uint32_t* p = &Ps[row * KST + c4];
        p[0] = f2tf32(tv.x * 0.125f);
        p[1] = f2tf32(tv.y * 0.125f);
        p[2] = f2tf32(tv.z * 0.125f);
        p[3] = f2tf32(tv.w * 0.125f);
    }
    __syncthreads();

    uint32_t qf[8][4];
    {
        int r0 = wid * 16 + g;
#pragma unroll
        for (int ks = 0; ks < 8; ++ks) {
            qf[ks][0] = Ps[r0 * KST + ks * 8 + t];
            qf[ks][1] = Ps[(r0 + 8) * KST + ks * 8 + t];
            qf[ks][2] = Ps[r0 * KST + ks * 8 + t + 4];
            qf[ks][3] = Ps[(r0 + 8) * KST + ks * 8 + t + 4];
        }
    }

    float o_acc[8][4];
#pragma unroll
    for (int nt = 0; nt < 8; ++nt)
#pragma unroll
        for (int r = 0; r < 4; ++r) o_acc[nt][r] = 0.f;
    float m0 = -INFINITY, m1 = -INFINITY, l0 = 0.f, l1 = 0.f;

    const float* kbase = k + ((size_t)b * LL * KVH + kvh) * DHH;
    const float* vbase = v + ((size_t)b * LL * KVH + kvh) * DHH;
    uint32_t* Pw = Ps + wid * 16 * KST;
    const int ntiles = bx + 1;

    for (int ti = 0; ti < ntiles; ++ti) {
        const int kb = ti * 64;
#pragma unroll
        for (int i = tid; i < 64 * 64 / 4; i += 128) {
            int row = i >> 4;
            int c4  = (i & 15) << 2;
            size_t goff = (size_t)(kb + row) * KVH * DHH + c4;
            float4 kv4 = *(const float4*)&kbase[goff];
            uint32_t* pk = &Ks[row * KST + c4];
            pk[0] = f2tf32(kv4.x); pk[1] = f2tf32(kv4.y);
            pk[2] = f2tf32(kv4.z); pk[3] = f2tf32(kv4.w);
            float4 vv4 = *(const float4*)&vbase[goff];
            uint32_t* pv = &Vs[row * VST + c4];
            pv[0] = f2tf32(vv4.x); pv[1] = f2tf32(vv4.y);
            pv[2] = f2tf32(vv4.z); pv[3] = f2tf32(vv4.w);
        }
        __syncthreads();

        float s_acc[8][4];
#pragma unroll
        for (int nt = 0; nt < 8; ++nt)
#pragma unroll
            for (int r = 0; r < 4; ++r) s_acc[nt][r] = 0.f;
#pragma unroll
        for (int ks = 0; ks < 8; ++ks) {
            uint32_t bfr[8][2];
#pragma unroll
            for (int nt = 0; nt < 8; ++nt) {
                bfr[nt][0] = Ks[(nt * 8 + g) * KST + ks * 8 + t];
                bfr[nt][1] = Ks[(nt * 8 + g) * KST + ks * 8 + t + 4];
            }
#pragma unroll
            for (int nt = 0; nt < 8; ++nt) mma_tf32(s_acc[nt], qf[ks], bfr[nt]);
        }

        const int wr = wid * 16 + g;
        if (ti == ntiles - 1) {
#pragma unroll
            for (int nt = 0; nt < 8; ++nt) {
                int c = nt * 8 + 2 * t;
                if (c > wr)          s_acc[nt][0] = -INFINITY;
                if (c + 1 > wr)      s_acc[nt][1] = -INFINITY;
                if (c > wr + 8)      s_acc[nt][2] = -INFINITY;
                if (c + 1 > wr + 8)  s_acc[nt][3] = -INFINITY;
            }
        }

        float tm0 = -INFINITY, tm1 = -INFINITY;
#pragma unroll
        for (int nt = 0; nt < 8; ++nt) {
            tm0 = fmaxf(tm0, fmaxf(s_acc[nt][0], s_acc[nt][1]));
            tm1 = fmaxf(tm1, fmaxf(s_acc[nt][2], s_acc[nt][3]));
        }
        tm0 = fmaxf(tm0, __shfl_xor_sync(0xffffffff, tm0, 1));
        tm0 = fmaxf(tm0, __shfl_xor_sync(0xffffffff, tm0, 2));
        tm1 = fmaxf(tm1, __shfl_xor_sync(0xffffffff, tm1, 1));
        tm1 = fmaxf(tm1, __shfl_xor_sync(0xffffffff, tm1, 2));
        float mn0 = fmaxf(m0, tm0), mn1 = fmaxf(m1, tm1);
        float a0 = __expf(m0 - mn0), a1 = __expf(m1 - mn1);
        float ps0 = 0.f, ps1 = 0.f;
#pragma unroll
        for (int nt = 0; nt < 8; ++nt) {
            s_acc[nt][0] = __expf(s_acc[nt][0] - mn0);
            s_acc[nt][1] = __expf(s_acc[nt][1] - mn0);
            s_acc[nt][2] = __expf(s_acc[nt][2] - mn1);
            s_acc[nt][3] = __expf(s_acc[nt][3] - mn1);
            ps0 += s_acc[nt][0] + s_acc[nt][1];
            ps1 += s_acc[nt][2] + s_acc[nt][3];
        }
        ps0 += __shfl_xor_sync(0xffffffff, ps0, 1);
        ps0 += __shfl_xor_sync(0xffffffff, ps0, 2);
        ps1 += __shfl_xor_sync(0xffffffff, ps1, 1);
        ps1 += __shfl_xor_sync(0xffffffff, ps1, 2);
        l0 = l0 * a0 + ps0;
        l1 = l1 * a1 + ps1;
        m0 = mn0; m1 = mn1;

#pragma unroll
        for (int nt = 0; nt < 8; ++nt) {
            int c = nt * 8 + 2 * t;
            Pw[g * KST + c]           = f2tf32(s_acc[nt][0]);
            Pw[g * KST + c + 1]       = f2tf32(s_acc[nt][1]);
            Pw[(g + 8) * KST + c]     = f2tf32(s_acc[nt][2]);
            Pw[(g + 8) * KST + c + 1] = f2tf32(s_acc[nt][3]);
        }
        __syncwarp();

#pragma unroll
        for (int nt = 0; nt < 8; ++nt) {
            o_acc[nt][0] *= a0; o_acc[nt][1] *= a0;
            o_acc[nt][2] *= a1; o_acc[nt][3] *= a1;
        }
#pragma unroll
        for (int ks = 0; ks < 8; ++ks) {
            uint32_t pf[4];
            pf[0] = Pw[g * KST + ks * 8 + t];
            pf[1] = Pw[(g + 8) * KST + ks * 8 + t];
            pf[2] = Pw[g * KST + ks * 8 + t + 4];
            pf[3] = Pw[(g + 8) * KST + ks * 8 + t + 4];
            uint32_t bv[8][2];
#pragma unroll
            for (int nt = 0; nt < 8; ++nt) {
                bv[nt][0] = Vs[(ks * 8 + t) * VST + nt * 8 + g];
                bv[nt][1] = Vs[(ks * 8 + t + 4) * VST + nt * 8 + g];
            }
#pragma unroll
            for (int nt = 0; nt < 8; ++nt) mma_tf32(o_acc[nt], pf, bv[nt]);
        }
        __syncthreads();
    }

    const float inv0 = 1.f / l0, inv1 = 1.f / l1;
    const int row0 = q0 + wid * 16 + g;
    float* obase  = o + ((size_t)((b * LL + row0) * HH + h)) * DHH;
    float* obase8 = o + ((size_t)((b * LL + row0 + 8) * HH + h)) * DHH;
#pragma unroll
    for (int nt = 0; nt < 8; ++nt) {
        int c = nt * 8 + 2 * t;
        *(float2*)&obase[c]  = make_float2(o_acc[nt][0] * inv0, o_acc[nt][1] * inv0);
        *(float2*)&obase8[c] = make_float2(o_acc[nt][2] * inv1, o_acc[nt][3] * inv1);
    }
}

// ---------------- launch ----------------
extern "C" void kernel_launch(void* const* d_in, const int* in_sizes, int n_in,
                              void* d_out, int out_size) {
    const float* x  = (const float*)d_in[0];
    const float* rc = (const float*)d_in[1];
    const float* rs = (const float*)d_in[2];
    const float* Wq = (const float*)d_in[3];
    const float* Wk = (const float*)d_in[4];
    const float* Wv = (const float*)d_in[5];
    const float* Wo = (const float*)d_in[6];
    float* out = (float*)d_out;

    float *q, *k, *v, *att;
    cudaGetSymbolAddress((void**)&q,   g_q);
    cudaGetSymbolAddress((void**)&k,   g_k);
    cudaGetSymbolAddress((void**)&v,   g_v);
    cudaGetSymbolAddress((void**)&att, g_att);

    static bool attr_set = false;
    const int attn_smem = (64 * KST + 64 * VST + 4 * 16 * KST) * 4;  // 53248 B
    if (!attr_set) {
        cudaFuncSetAttribute(gemm_qkv_kernel,
                             cudaFuncAttributeMaxDynamicSharedMemorySize, GEMM_SMEM);
        cudaFuncSetAttribute(gemm_wo_kernel,
                             cudaFuncAttributeMaxDynamicSharedMemorySize, GEMM_SMEM);
        cudaFuncSetAttribute(attn_mma_kernel,
                             cudaFuncAttributeMaxDynamicSharedMemorySize, attn_smem);
        attr_set = true;
    }

    // merged QKV projection (tf32 tensor cores, cp.async pipelined)
    gemm_qkv_kernel<<<dim3(24, MROWS / 128), 256, GEMM_SMEM>>>(x, Wq, Wk, Wv, q, k, v);

    // RoPE on q and k
    {
        int tq = BB * LL * HH * (DHH / 2);
        rope_kernel<<<(tq + 255) / 256, 256>>>(q, rc, rs, HH);
        int tk = BB * LL * KVH * (DHH / 2);
        rope_kernel<<<(tk + 255) / 256, 256>>>(k, rc, rs, KVH);
    }

    // attention (tf32 tensor cores, flash)
    attn_mma_kernel<<<dim3(LL / 64, BB * HH), 128, attn_smem>>>(q, k, v, att);

    // output projection -> d_out
    gemm_wo_kernel<<<dim3(DD / 64, MROWS / 128), 256, GEMM_SMEM>>>(att, Wo, out, DD, DD);
}